// round 2
// baseline (speedup 1.0000x reference)
#include <cuda_runtime.h>

// AttentionConv: q,k,v = 1x1 convs; per-channel softmax over 7x7 window of
// q*(k+bias); out = sum attn*v.  B=4, C=Cout=64, H=W=64, K=7, PAD=3.
//
// R2: qkv rebuilt as FFMA2-bound GEMM (8o x 4px register tile, broadcast
//     duplicated weights, natural x pairs). attn strip loads vectorized
//     (stride 76, aligned LDS.128).

#define LOG2E 1.4426950408889634f

__device__ float g_q[4 * 64 * 64 * 64];
__device__ float g_k[4 * 64 * 64 * 64];
__device__ float g_v[4 * 64 * 64 * 64];

__device__ __forceinline__ float ex2f(float v) {
    float r;
    asm("ex2.approx.ftz.f32 %0, %1;" : "=f"(r) : "f"(v));
    return r;
}

__device__ __forceinline__ unsigned long long fma_f32x2(
    unsigned long long a, unsigned long long b, unsigned long long c) {
    unsigned long long d;
    asm("fma.rn.f32x2 %0, %1, %2, %3;" : "=l"(d) : "l"(a), "l"(b), "l"(c));
    return d;
}

// ---------------------------------------------------------------------------
// Kernel 1: qkv projections.  Block: 128 threads, 64o x 64px tile.
// smem: ws2[c][o] duplicated weight pairs (32KB, read as 16-way warp
// broadcast), xs[c][p] (16KB).  Thread tile 8o x 4px -> 16 FFMA2 per c.
// Crossbar ~24 cyc/block/c vs 32 cyc FFMA2 -> FFMA2-bound.
// ---------------------------------------------------------------------------
__global__ __launch_bounds__(128) void qkv_kernel(
    const float* __restrict__ x, const float* __restrict__ y,
    const float* __restrict__ Wq, const float* __restrict__ Wk,
    const float* __restrict__ Wv) {
    __shared__ float2 ws2[64 * 64];   // 32768 B  [c*64 + o] = (W[o][c], W[o][c])
    __shared__ float  xs[64 * 64];    // 16384 B  [c*64 + p]

    const int mat = blockIdx.y;
    const float* Wsrc = (mat == 0) ? Wq : ((mat == 1) ? Wk : Wv);
    const float* src  = (mat == 2) ? y : x;
    float* dst = (mat == 0) ? g_q : ((mat == 1) ? g_k : g_v);

    const int tid = threadIdx.x;
    const int pix0 = blockIdx.x * 64;      // 64 consecutive pixels, same b
    const int b = pix0 >> 12;
    const int hw0 = pix0 & 4095;

    // weights: read transposed (L2-hot), write coalesced+duplicated
#pragma unroll
    for (int i = 0; i < 32; i++) {
        int idx = tid + i * 128;           // c*64 + o
        float w = Wsrc[(idx & 63) * 64 + (idx >> 6)];
        ws2[idx] = make_float2(w, w);
    }
#pragma unroll
    for (int i = 0; i < 32; i++) {
        int idx = tid + i * 128;           // c*64 + p
        int c = idx >> 6, p = idx & 63;
        xs[idx] = src[((b << 6) + c) * 4096 + hw0 + p];
    }
    __syncthreads();

    const int o0 = (tid >> 4) << 3;        // 8 outputs per thread
    const int p0 = (tid & 15) << 2;        // 4 pixels per thread

    unsigned long long acc[8][2];
#pragma unroll
    for (int i = 0; i < 8; i++) { acc[i][0] = 0ULL; acc[i][1] = 0ULL; }

#pragma unroll 8
    for (int c = 0; c < 64; c++) {
        ulonglong2 xv = *(const ulonglong2*)(xs + (c << 6) + p0);
        const ulonglong2* wp = (const ulonglong2*)(ws2 + (c << 6) + o0);
        ulonglong2 w01 = wp[0];
        ulonglong2 w23 = wp[1];
        ulonglong2 w45 = wp[2];
        ulonglong2 w67 = wp[3];
        acc[0][0] = fma_f32x2(w01.x, xv.x, acc[0][0]);
        acc[0][1] = fma_f32x2(w01.x, xv.y, acc[0][1]);
        acc[1][0] = fma_f32x2(w01.y, xv.x, acc[1][0]);
        acc[1][1] = fma_f32x2(w01.y, xv.y, acc[1][1]);
        acc[2][0] = fma_f32x2(w23.x, xv.x, acc[2][0]);
        acc[2][1] = fma_f32x2(w23.x, xv.y, acc[2][1]);
        acc[3][0] = fma_f32x2(w23.y, xv.x, acc[3][0]);
        acc[3][1] = fma_f32x2(w23.y, xv.y, acc[3][1]);
        acc[4][0] = fma_f32x2(w45.x, xv.x, acc[4][0]);
        acc[4][1] = fma_f32x2(w45.x, xv.y, acc[4][1]);
        acc[5][0] = fma_f32x2(w45.y, xv.x, acc[5][0]);
        acc[5][1] = fma_f32x2(w45.y, xv.y, acc[5][1]);
        acc[6][0] = fma_f32x2(w67.x, xv.x, acc[6][0]);
        acc[6][1] = fma_f32x2(w67.x, xv.y, acc[6][1]);
        acc[7][0] = fma_f32x2(w67.y, xv.x, acc[7][0]);
        acc[7][1] = fma_f32x2(w67.y, xv.y, acc[7][1]);
    }

#pragma unroll
    for (int oi = 0; oi < 8; oi++) {
        float2 a0 = *reinterpret_cast<float2*>(&acc[oi][0]);
        float2 a1 = *reinterpret_cast<float2*>(&acc[oi][1]);
        float4 r = make_float4(a0.x, a0.y, a1.x, a1.y);
        *(float4*)(dst + ((b << 6) + o0 + oi) * 4096 + hw0 + p0) = r;
    }
}

// ---------------------------------------------------------------------------
// Kernel 2: windowed per-channel softmax-attention.
// grid = (4 h-tiles, 64 channels, 4 batches); block = 256 threads.
// Shared: zero-padded k/v halo tile, stride 76 (x4 aligned) so each 12-wide
// strip is 3x LDS.128. Single-pass no-max softmax via ex2.approx.
// ---------------------------------------------------------------------------
#define KSW 76

__global__ __launch_bounds__(256) void attn_kernel(
    const float* __restrict__ rel_h, const float* __restrict__ rel_w,
    float* __restrict__ out) {
    __shared__ float ks[22 * KSW];
    __shared__ float vs[22 * KSW];
    __shared__ float sbias[49];

    const int tid = threadIdx.x;
    const int h0 = blockIdx.x << 4;        // 16-row tile
    const int c  = blockIdx.y;
    const int b  = blockIdx.z;
    const int plane = ((b << 6) + c) << 12;

    for (int i = tid; i < 22 * KSW; i += 256) { ks[i] = 0.0f; vs[i] = 0.0f; }
    if (tid < 49) {
        int kh = tid / 7, kw = tid % 7;
        sbias[tid] = (c < 32) ? rel_h[c * 7 + kh] : rel_w[(c - 32) * 7 + kw];
    }
    __syncthreads();

    const float* kp = g_k + plane;
    const float* vp = g_v + plane;
    for (int i = tid; i < 22 * 64; i += 256) {
        int r = i >> 6, cc = i & 63;
        int gr = h0 - 3 + r;
        if (gr >= 0 && gr < 64) {
            ks[r * KSW + cc + 3] = kp[(gr << 6) + cc];
            vs[r * KSW + cc + 3] = vp[(gr << 6) + cc];
        }
    }
    __syncthreads();

    const int ty = tid >> 4;               // 0..15 row in tile
    const int w0 = (tid & 15) << 2;        // 4 outputs along w
    const int h = h0 + ty;

    const float4 q4 = *(const float4*)(g_q + plane + (h << 6) + w0);
    float q2[4] = {q4.x * LOG2E, q4.y * LOG2E, q4.z * LOG2E, q4.w * LOG2E};
    float s[4] = {0.f, 0.f, 0.f, 0.f};
    float a[4] = {0.f, 0.f, 0.f, 0.f};

#pragma unroll 7
    for (int hh = 0; hh < 7; hh++) {
        // base = row*76 + w0: 16B aligned (76, w0 both mult of 4).
        // kr[j] = k[h-3+hh][w0-3+j]  (left pad 3 puts col w0-3 at index w0)
        const float* krow = &ks[(ty + hh) * KSW + w0];
        const float* vrow = &vs[(ty + hh) * KSW + w0];
        float kr[12], vr[12];
        *(float4*)(kr)     = *(const float4*)(krow);
        *(float4*)(kr + 4) = *(const float4*)(krow + 4);
        *(float4*)(kr + 8) = *(const float4*)(krow + 8);
        *(float4*)(vr)     = *(const float4*)(vrow);
        *(float4*)(vr + 4) = *(const float4*)(vrow + 4);
        *(float4*)(vr + 8) = *(const float4*)(vrow + 8);
#pragma unroll
        for (int kw = 0; kw < 7; kw++) {
            float bb = sbias[hh * 7 + kw];
#pragma unroll
            for (int i = 0; i < 4; i++) {
                float e = ex2f(q2[i] * (kr[i + kw] + bb));
                s[i] += e;
                a[i] = fmaf(e, vr[i + kw], a[i]);
            }
        }
    }

    float4 o4;
    o4.x = __fdividef(a[0], s[0]);
    o4.y = __fdividef(a[1], s[1]);
    o4.z = __fdividef(a[2], s[2]);
    o4.w = __fdividef(a[3], s[3]);
    *(float4*)(out + plane + (h << 6) + w0) = o4;
}

extern "C" void kernel_launch(void* const* d_in, const int* in_sizes, int n_in,
                              void* d_out, int out_size) {
    const float* x     = (const float*)d_in[0];
    const float* y     = (const float*)d_in[1];
    const float* Wq    = (const float*)d_in[2];
    const float* Wk    = (const float*)d_in[3];
    const float* Wv    = (const float*)d_in[4];
    const float* rel_h = (const float*)d_in[5];
    const float* rel_w = (const float*)d_in[6];
    float* out = (float*)d_out;

    dim3 g1(256, 3, 1);
    qkv_kernel<<<g1, 128>>>(x, y, Wq, Wk, Wv);

    dim3 g2(4, 64, 4);
    attn_kernel<<<g2, 256>>>(rel_h, rel_w, out);
}

// round 3
// speedup vs baseline: 1.5076x; 1.5076x over previous
#include <cuda_runtime.h>

// AttentionConv: q,k,v = 1x1 convs; per-channel softmax over 7x7 window of
// q*(k+bias); out = sum attn*v.  B=4, C=Cout=64, H=W=64, K=7, PAD=3.
//
// R3: qkv prologue made coalesced (the R1/R2 killer was a 256B-strided
//     uncoalesced weight gather: ~4096 L1 wavefronts/block). FFMA2 packed
//     over o-pairs (natural weight pairs from W^T, x duplicated via MOV).
//     attn: 2 rows/thread with shared sliding strips, bias hoisting for
//     c<32, 128-thread blocks -> 7 blocks/SM, single wave.

#define LOG2E 1.4426950408889634f

__device__ float g_q[4 * 64 * 64 * 64];
__device__ float g_k[4 * 64 * 64 * 64];
__device__ float g_v[4 * 64 * 64 * 64];

__device__ __forceinline__ float ex2f(float v) {
    float r;
    asm("ex2.approx.ftz.f32 %0, %1;" : "=f"(r) : "f"(v));
    return r;
}

__device__ __forceinline__ unsigned long long fma_f32x2(
    unsigned long long a, unsigned long long b, unsigned long long c) {
    unsigned long long d;
    asm("fma.rn.f32x2 %0, %1, %2, %3;" : "=l"(d) : "l"(a), "l"(b), "l"(c));
    return d;
}

__device__ __forceinline__ unsigned long long dupf(float v) {
    unsigned long long r;
    asm("mov.b64 %0, {%1, %1};" : "=l"(r) : "f"(v));
    return r;
}

// ---------------------------------------------------------------------------
// Kernel 1: qkv projections.  128 threads, 64o x 64px tile, 768 blocks.
// smem: ws[c][o] = W^T, row stride 66 floats (coalesced LDG + 2-way STS
// scatter); xs[c][p].  Thread tile 8o x 4px as 4 o-pairs: per c load 4
// natural float2 weight pairs (broadcast) + 1 float4 x + 4 dup MOVs ->
// 16 FFMA2.  fma-pipe bound: ~32 cyc/c/warp.
// ---------------------------------------------------------------------------
#define WSTR 66

__global__ __launch_bounds__(128) void qkv_kernel(
    const float* __restrict__ x, const float* __restrict__ y,
    const float* __restrict__ Wq, const float* __restrict__ Wk,
    const float* __restrict__ Wv) {
    __shared__ __align__(16) float ws[64 * WSTR];   // [c*66 + o]
    __shared__ __align__(16) float xs[64 * 64];     // [c*64 + p]

    const int mat = blockIdx.y;
    const float* Wsrc = (mat == 0) ? Wq : ((mat == 1) ? Wk : Wv);
    const float* src  = (mat == 2) ? y : x;
    float* dst = (mat == 0) ? g_q : ((mat == 1) ? g_k : g_v);

    const int tid = threadIdx.x;
    const int pix0 = blockIdx.x * 64;      // 64 consecutive pixels, same b
    const int b = pix0 >> 12;
    const int hw0 = pix0 & 4095;

    // coalesced weight read (flat o*64+c), scatter-transpose into smem
#pragma unroll
    for (int i = 0; i < 32; i++) {
        int idx = tid + i * 128;           // = o*64 + c
        ws[(idx & 63) * WSTR + (idx >> 6)] = Wsrc[idx];
    }
#pragma unroll
    for (int i = 0; i < 32; i++) {
        int idx = tid + i * 128;           // = c*64 + p
        xs[idx] = src[((b << 6) + (idx >> 6)) * 4096 + hw0 + (idx & 63)];
    }
    __syncthreads();

    const int o0 = (tid >> 4) << 3;        // 8 outputs (4 o-pairs)
    const int p0 = (tid & 15) << 2;        // 4 pixels

    unsigned long long acc[4][4];          // [o_pair][pixel]
#pragma unroll
    for (int i = 0; i < 4; i++)
#pragma unroll
        for (int j = 0; j < 4; j++) acc[i][j] = 0ULL;

#pragma unroll 4
    for (int cc = 0; cc < 64; cc++) {
        float4 xv = *(const float4*)(xs + (cc << 6) + p0);
        unsigned long long dx0 = dupf(xv.x);
        unsigned long long dx1 = dupf(xv.y);
        unsigned long long dx2 = dupf(xv.z);
        unsigned long long dx3 = dupf(xv.w);
        const float* wrow = ws + cc * WSTR + o0;
        unsigned long long wp0 = *(const unsigned long long*)(wrow);
        unsigned long long wp1 = *(const unsigned long long*)(wrow + 2);
        unsigned long long wp2 = *(const unsigned long long*)(wrow + 4);
        unsigned long long wp3 = *(const unsigned long long*)(wrow + 6);
        acc[0][0] = fma_f32x2(wp0, dx0, acc[0][0]);
        acc[0][1] = fma_f32x2(wp0, dx1, acc[0][1]);
        acc[0][2] = fma_f32x2(wp0, dx2, acc[0][2]);
        acc[0][3] = fma_f32x2(wp0, dx3, acc[0][3]);
        acc[1][0] = fma_f32x2(wp1, dx0, acc[1][0]);
        acc[1][1] = fma_f32x2(wp1, dx1, acc[1][1]);
        acc[1][2] = fma_f32x2(wp1, dx2, acc[1][2]);
        acc[1][3] = fma_f32x2(wp1, dx3, acc[1][3]);
        acc[2][0] = fma_f32x2(wp2, dx0, acc[2][0]);
        acc[2][1] = fma_f32x2(wp2, dx1, acc[2][1]);
        acc[2][2] = fma_f32x2(wp2, dx2, acc[2][2]);
        acc[2][3] = fma_f32x2(wp2, dx3, acc[2][3]);
        acc[3][0] = fma_f32x2(wp3, dx0, acc[3][0]);
        acc[3][1] = fma_f32x2(wp3, dx1, acc[3][1]);
        acc[3][2] = fma_f32x2(wp3, dx2, acc[3][2]);
        acc[3][3] = fma_f32x2(wp3, dx3, acc[3][3]);
    }

#pragma unroll
    for (int o2 = 0; o2 < 4; o2++) {
        float2 v0 = *reinterpret_cast<float2*>(&acc[o2][0]);
        float2 v1 = *reinterpret_cast<float2*>(&acc[o2][1]);
        float2 v2 = *reinterpret_cast<float2*>(&acc[o2][2]);
        float2 v3 = *reinterpret_cast<float2*>(&acc[o2][3]);
        float* base = dst + ((b << 6) + o0 + 2 * o2) * 4096 + hw0 + p0;
        *(float4*)(base)        = make_float4(v0.x, v1.x, v2.x, v3.x);
        *(float4*)(base + 4096) = make_float4(v0.y, v1.y, v2.y, v3.y);
    }
}

// ---------------------------------------------------------------------------
// Kernel 2: windowed per-channel softmax-attention.
// grid = (4 h-tiles, 64 channels, 4 batches); block = 128 threads.
// Block: 16 rows x 64 cols of one (b,c) plane; thread: 2 rows x 4 cols.
// Sliding over 8 window rows: each 12-wide k/v strip serves both output
// rows.  Bias hoisted out of kw loop when c<32 (rel_h depends on kh only).
// Single-pass no-max softmax via ex2.approx (|log2 logit| < 128).
// ---------------------------------------------------------------------------
#define KSW 76

__global__ __launch_bounds__(128, 7) void attn_kernel(
    const float* __restrict__ rel_h, const float* __restrict__ rel_w,
    float* __restrict__ out) {
    __shared__ __align__(16) float ks[22 * KSW];
    __shared__ __align__(16) float vs[22 * KSW];

    const int tid = threadIdx.x;
    const int h0 = blockIdx.x << 4;        // 16-row tile
    const int c  = blockIdx.y;
    const int b  = blockIdx.z;
    const int plane = ((b << 6) + c) << 12;

    // bias: 7 values, uniform per block (kh-indexed for c<32, kw for c>=32)
    const float* bp = (c < 32) ? (rel_h + c * 7) : (rel_w + (c - 32) * 7);
    float bias7[7];
#pragma unroll
    for (int j = 0; j < 7; j++) bias7[j] = __ldg(bp + j);

    // zero-fill padded tiles (vectorized)
    float4 z4 = make_float4(0.f, 0.f, 0.f, 0.f);
    for (int i = tid; i < (22 * KSW) / 4; i += 128) {
        ((float4*)ks)[i] = z4;
        ((float4*)vs)[i] = z4;
    }
    __syncthreads();

    // interior: rows h0-3 .. h0+18, cols 0..63 -> padded col +3
    const float* kp = g_k + plane;
    const float* vp = g_v + plane;
    for (int i = tid; i < 22 * 16; i += 128) {
        int r = i >> 4, c4 = (i & 15) << 2;
        int gr = h0 - 3 + r;
        if ((unsigned)gr < 64u) {
            float4 kv = *(const float4*)(kp + (gr << 6) + c4);
            float4 vv = *(const float4*)(vp + (gr << 6) + c4);
            int s0 = r * KSW + 3 + c4;
            ks[s0] = kv.x; ks[s0 + 1] = kv.y; ks[s0 + 2] = kv.z; ks[s0 + 3] = kv.w;
            vs[s0] = vv.x; vs[s0 + 1] = vv.y; vs[s0 + 2] = vv.z; vs[s0 + 3] = vv.w;
        }
    }
    __syncthreads();

    const int ty = tid >> 4;               // 0..7 -> output rows 2ty, 2ty+1
    const int w0 = (tid & 15) << 2;        // 4 outputs along w
    const int r0 = h0 + (ty << 1);

    const float4 qa = *(const float4*)(g_q + plane + (r0 << 6) + w0);
    const float4 qb = *(const float4*)(g_q + plane + ((r0 + 1) << 6) + w0);
    float q2[8] = {qa.x * LOG2E, qa.y * LOG2E, qa.z * LOG2E, qa.w * LOG2E,
                   qb.x * LOG2E, qb.y * LOG2E, qb.z * LOG2E, qb.w * LOG2E};
    float s[8], a[8];
#pragma unroll
    for (int i = 0; i < 8; i++) { s[i] = 0.f; a[i] = 0.f; }

    if (c < 32) {
        // bias depends on kh only: hoist q2*bias out of the kw loop
#pragma unroll
        for (int j = 0; j < 8; j++) {
            const float* krow = &ks[((ty << 1) + j) * KSW + w0];
            const float* vrow = &vs[((ty << 1) + j) * KSW + w0];
            float kr[12], vr[12];
            *(float4*)(kr)     = *(const float4*)(krow);
            *(float4*)(kr + 4) = *(const float4*)(krow + 4);
            *(float4*)(kr + 8) = *(const float4*)(krow + 8);
            *(float4*)(vr)     = *(const float4*)(vrow);
            *(float4*)(vr + 4) = *(const float4*)(vrow + 4);
            *(float4*)(vr + 8) = *(const float4*)(vrow + 8);
            if (j < 7) {                   // row0, hh = j
                float qb0[4];
#pragma unroll
                for (int i = 0; i < 4; i++) qb0[i] = q2[i] * bias7[j];
#pragma unroll
                for (int kw = 0; kw < 7; kw++)
#pragma unroll
                    for (int i = 0; i < 4; i++) {
                        float e = ex2f(fmaf(q2[i], kr[i + kw], qb0[i]));
                        s[i] += e;
                        a[i] = fmaf(e, vr[i + kw], a[i]);
                    }
            }
            if (j >= 1) {                  // row1, hh = j-1
                float qb1[4];
#pragma unroll
                for (int i = 0; i < 4; i++) qb1[i] = q2[4 + i] * bias7[j - 1];
#pragma unroll
                for (int kw = 0; kw < 7; kw++)
#pragma unroll
                    for (int i = 0; i < 4; i++) {
                        float e = ex2f(fmaf(q2[4 + i], kr[i + kw], qb1[i]));
                        s[4 + i] += e;
                        a[4 + i] = fmaf(e, vr[i + kw], a[4 + i]);
                    }
            }
        }
    } else {
        // bias depends on kw only
#pragma unroll
        for (int j = 0; j < 8; j++) {
            const float* krow = &ks[((ty << 1) + j) * KSW + w0];
            const float* vrow = &vs[((ty << 1) + j) * KSW + w0];
            float kr[12], vr[12];
            *(float4*)(kr)     = *(const float4*)(krow);
            *(float4*)(kr + 4) = *(const float4*)(krow + 4);
            *(float4*)(kr + 8) = *(const float4*)(krow + 8);
            *(float4*)(vr)     = *(const float4*)(vrow);
            *(float4*)(vr + 4) = *(const float4*)(vrow + 4);
            *(float4*)(vr + 8) = *(const float4*)(vrow + 8);
            if (j < 7) {
#pragma unroll
                for (int kw = 0; kw < 7; kw++) {
                    float bb = bias7[kw];
#pragma unroll
                    for (int i = 0; i < 4; i++) {
                        float e = ex2f(q2[i] * (kr[i + kw] + bb));
                        s[i] += e;
                        a[i] = fmaf(e, vr[i + kw], a[i]);
                    }
                }
            }
            if (j >= 1) {
#pragma unroll
                for (int kw = 0; kw < 7; kw++) {
                    float bb = bias7[kw];
#pragma unroll
                    for (int i = 0; i < 4; i++) {
                        float e = ex2f(q2[4 + i] * (kr[i + kw] + bb));
                        s[4 + i] += e;
                        a[4 + i] = fmaf(e, vr[i + kw], a[4 + i]);
                    }
                }
            }
        }
    }

    float4 o0, o1;
    o0.x = __fdividef(a[0], s[0]);
    o0.y = __fdividef(a[1], s[1]);
    o0.z = __fdividef(a[2], s[2]);
    o0.w = __fdividef(a[3], s[3]);
    o1.x = __fdividef(a[4], s[4]);
    o1.y = __fdividef(a[5], s[5]);
    o1.z = __fdividef(a[6], s[6]);
    o1.w = __fdividef(a[7], s[7]);
    *(float4*)(out + plane + (r0 << 6) + w0) = o0;
    *(float4*)(out + plane + ((r0 + 1) << 6) + w0) = o1;
}

extern "C" void kernel_launch(void* const* d_in, const int* in_sizes, int n_in,
                              void* d_out, int out_size) {
    const float* x     = (const float*)d_in[0];
    const float* y     = (const float*)d_in[1];
    const float* Wq    = (const float*)d_in[2];
    const float* Wk    = (const float*)d_in[3];
    const float* Wv    = (const float*)d_in[4];
    const float* rel_h = (const float*)d_in[5];
    const float* rel_w = (const float*)d_in[6];
    float* out = (float*)d_out;

    dim3 g1(256, 3, 1);
    qkv_kernel<<<g1, 128>>>(x, y, Wq, Wk, Wv);

    dim3 g2(4, 64, 4);
    attn_kernel<<<g2, 128>>>(rel_h, rel_w, out);
}